// round 3
// baseline (speedup 1.0000x reference)
#include <cuda_runtime.h>
#include <math.h>

#define N_TOK   8192
#define D_MODEL 1024
#define H_DIM   512
#define N_EXP   8
#define TOPK    2
#define N_ASSIGN (N_TOK * TOPK)
#define TILE_M  128
#define MAX_TILES (N_ASSIGN / TILE_M + N_EXP)   // 136

// ---- scratch (device globals: no allocation in kernel_launch) ----
__device__ float g_h[N_ASSIGN * H_DIM];          // fc1 activations, expert-sorted rows
__device__ int   g_counts[N_EXP];
__device__ int   g_offsets[N_EXP + 1];
__device__ int   g_cursors[N_EXP];
__device__ int   g_rowToken[N_ASSIGN];           // sorted assignment -> token
__device__ float g_tokw[N_TOK];                  // sum of top-2 gate probs
__device__ int   g_tokExperts[N_TOK * TOPK];
__device__ int   g_tileExpert[MAX_TILES];
__device__ int   g_tileRowStart[MAX_TILES];
__device__ int   g_tileRows[MAX_TILES];
__device__ int   g_numTiles;

// ---------------- init: zero output + counts (must run every replay) ----------------
__global__ void init_kernel(float* __restrict__ out) {
    int idx = blockIdx.x * blockDim.x + threadIdx.x;
    // out has N_TOK * D_MODEL = 8388608 floats = 2097152 float4
    if (idx < (N_TOK * D_MODEL) / 4) {
        ((float4*)out)[idx] = make_float4(0.f, 0.f, 0.f, 0.f);
    }
    if (idx < N_EXP) g_counts[idx] = 0;
}

// ---------------- gating: one block (256 thr) per token ----------------
__global__ void gate_kernel(const float* __restrict__ x, const float* __restrict__ gw) {
    int n = blockIdx.x;
    int tid = threadIdx.x;
    const float* xr = x + (size_t)n * D_MODEL;
    float acc[N_EXP];
#pragma unroll
    for (int e = 0; e < N_EXP; e++) acc[e] = 0.f;
    for (int d = tid; d < D_MODEL; d += 256) {
        float xv = xr[d];
        const float* g = gw + d * N_EXP;
#pragma unroll
        for (int e = 0; e < N_EXP; e++) acc[e] += xv * g[e];
    }
    // warp reduce
#pragma unroll
    for (int off = 16; off > 0; off >>= 1) {
#pragma unroll
        for (int e = 0; e < N_EXP; e++)
            acc[e] += __shfl_down_sync(0xffffffffu, acc[e], off);
    }
    __shared__ float s[8][N_EXP];
    int w = tid >> 5, l = tid & 31;
    if (l == 0) {
#pragma unroll
        for (int e = 0; e < N_EXP; e++) s[w][e] = acc[e];
    }
    __syncthreads();
    if (tid == 0) {
        float p[N_EXP];
#pragma unroll
        for (int e = 0; e < N_EXP; e++) {
            float v = 0.f;
#pragma unroll
            for (int ww = 0; ww < 8; ww++) v += s[ww][e];
            p[e] = v;
        }
        // softmax
        float mx = p[0];
#pragma unroll
        for (int e = 1; e < N_EXP; e++) mx = fmaxf(mx, p[e]);
        float sum = 0.f;
#pragma unroll
        for (int e = 0; e < N_EXP; e++) { p[e] = expf(p[e] - mx); sum += p[e]; }
        float inv = 1.f / sum;
#pragma unroll
        for (int e = 0; e < N_EXP; e++) p[e] *= inv;
        // top-2 (lowest index wins ties, matching lax.top_k)
        int i1 = 0;
#pragma unroll
        for (int e = 1; e < N_EXP; e++) if (p[e] > p[i1]) i1 = e;
        int i2 = (i1 == 0) ? 1 : 0;
#pragma unroll
        for (int e = 0; e < N_EXP; e++) if (e != i1 && p[e] > p[i2]) i2 = e;
        g_tokw[n] = p[i1] + p[i2];
        g_tokExperts[2 * n + 0] = i1;
        g_tokExperts[2 * n + 1] = i2;
        atomicAdd(&g_counts[i1], 1);
        atomicAdd(&g_counts[i2], 1);
    }
}

// ---------------- setup: offsets + tile descriptors (1 thread) ----------------
__global__ void setup_kernel() {
    int off = 0;
    for (int e = 0; e < N_EXP; e++) {
        g_offsets[e] = off;
        g_cursors[e] = off;
        off += g_counts[e];
    }
    g_offsets[N_EXP] = off;
    int t = 0;
    for (int e = 0; e < N_EXP; e++) {
        int c = g_counts[e];
        for (int r = 0; r < c; r += TILE_M) {
            g_tileExpert[t]   = e;
            g_tileRowStart[t] = g_offsets[e] + r;
            g_tileRows[t]     = min(TILE_M, c - r);
            t++;
        }
    }
    g_numTiles = t;
}

// ---------------- scatter: token -> expert-sorted assignment rows ----------------
__global__ void scatter_kernel() {
    int n = blockIdx.x * blockDim.x + threadIdx.x;
    if (n >= N_TOK) return;
#pragma unroll
    for (int k = 0; k < TOPK; k++) {
        int e = g_tokExperts[2 * n + k];
        int pos = atomicAdd(&g_cursors[e], 1);
        g_rowToken[pos] = n;
    }
}

__device__ __forceinline__ float gelu_exact(float v) {
    return 0.5f * v * (1.0f + erff(v * 0.70710678118654752f));
}

// ---------------- fc1: grouped SGEMM 128x128x8, A gathered from x ----------------
// grid (MAX_TILES, H_DIM/128), block 256
__global__ void __launch_bounds__(256)
fc1_kernel(const float* __restrict__ x, const float* __restrict__ w1,
           const float* __restrict__ b1) {
    int tile = blockIdx.x;
    if (tile >= g_numTiles) return;
    int e  = g_tileExpert[tile];
    int rs = g_tileRowStart[tile];
    int nr = g_tileRows[tile];
    int n0 = blockIdx.y * 128;

    __shared__ float As[8][128];
    __shared__ float Bs[8][128];

    int tid = threadIdx.x;
    int tx = tid & 15, ty = tid >> 4;

    int arow  = tid >> 1;            // 0..127
    int acol4 = (tid & 1) * 4;       // 0 or 4
    int token = (arow < nr) ? g_rowToken[rs + arow] : -1;
    const float* arow_ptr = (token >= 0) ? (x + (size_t)token * D_MODEL) : x;

    int brow  = tid >> 5;            // 0..7
    int bcol4 = (tid & 31) * 4;      // 0..124
    const float* B = w1 + (size_t)e * D_MODEL * H_DIM;

    float c[8][8];
#pragma unroll
    for (int i = 0; i < 8; i++)
#pragma unroll
        for (int j = 0; j < 8; j++) c[i][j] = 0.f;

    for (int k0 = 0; k0 < D_MODEL; k0 += 8) {
        float4 av = make_float4(0.f, 0.f, 0.f, 0.f);
        if (token >= 0) av = *(const float4*)(arow_ptr + k0 + acol4);
        As[acol4 + 0][arow] = av.x;
        As[acol4 + 1][arow] = av.y;
        As[acol4 + 2][arow] = av.z;
        As[acol4 + 3][arow] = av.w;
        float4 bv = *(const float4*)(B + (size_t)(k0 + brow) * H_DIM + n0 + bcol4);
        *(float4*)&Bs[brow][bcol4] = bv;
        __syncthreads();
#pragma unroll
        for (int k = 0; k < 8; k++) {
            float4 a0 = *(const float4*)&As[k][ty * 8];
            float4 a1 = *(const float4*)&As[k][ty * 8 + 4];
            float4 b0 = *(const float4*)&Bs[k][tx * 8];
            float4 b1v = *(const float4*)&Bs[k][tx * 8 + 4];
            float ar[8] = {a0.x, a0.y, a0.z, a0.w, a1.x, a1.y, a1.z, a1.w};
            float br[8] = {b0.x, b0.y, b0.z, b0.w, b1v.x, b1v.y, b1v.z, b1v.w};
#pragma unroll
            for (int i = 0; i < 8; i++)
#pragma unroll
                for (int j = 0; j < 8; j++) c[i][j] += ar[i] * br[j];
        }
        __syncthreads();
    }

    const float* b1e = b1 + e * H_DIM;
#pragma unroll
    for (int i = 0; i < 8; i++) {
        int m = ty * 8 + i;
        if (m < nr) {
            int r = rs + m;
#pragma unroll
            for (int j = 0; j < 8; j++) {
                int n = n0 + tx * 8 + j;
                g_h[(size_t)r * H_DIM + n] = gelu_exact(c[i][j] + b1e[n]);
            }
        }
    }
}

// ---------------- fc2: grouped SGEMM 128x128x8, A = g_h, atomic epilogue ----------------
// grid (MAX_TILES, D_MODEL/128), block 256
__global__ void __launch_bounds__(256)
fc2_kernel(const float* __restrict__ w2, const float* __restrict__ b2,
           float* __restrict__ out) {
    int tile = blockIdx.x;
    if (tile >= g_numTiles) return;
    int e  = g_tileExpert[tile];
    int rs = g_tileRowStart[tile];
    int nr = g_tileRows[tile];
    int n0 = blockIdx.y * 128;

    __shared__ float As[8][128];
    __shared__ float Bs[8][128];

    int tid = threadIdx.x;
    int tx = tid & 15, ty = tid >> 4;

    int arow  = tid >> 1;
    int acol4 = (tid & 1) * 4;
    const float* arow_ptr = g_h + (size_t)(rs + arow) * H_DIM;
    bool avalid = (arow < nr);

    int brow  = tid >> 5;
    int bcol4 = (tid & 31) * 4;
    const float* B = w2 + (size_t)e * H_DIM * D_MODEL;

    float c[8][8];
#pragma unroll
    for (int i = 0; i < 8; i++)
#pragma unroll
        for (int j = 0; j < 8; j++) c[i][j] = 0.f;

    for (int k0 = 0; k0 < H_DIM; k0 += 8) {
        float4 av = make_float4(0.f, 0.f, 0.f, 0.f);
        if (avalid) av = *(const float4*)(arow_ptr + k0 + acol4);
        As[acol4 + 0][arow] = av.x;
        As[acol4 + 1][arow] = av.y;
        As[acol4 + 2][arow] = av.z;
        As[acol4 + 3][arow] = av.w;
        float4 bv = *(const float4*)(B + (size_t)(k0 + brow) * D_MODEL + n0 + bcol4);
        *(float4*)&Bs[brow][bcol4] = bv;
        __syncthreads();
#pragma unroll
        for (int k = 0; k < 8; k++) {
            float4 a0 = *(const float4*)&As[k][ty * 8];
            float4 a1 = *(const float4*)&As[k][ty * 8 + 4];
            float4 b0 = *(const float4*)&Bs[k][tx * 8];
            float4 b1v = *(const float4*)&Bs[k][tx * 8 + 4];
            float ar[8] = {a0.x, a0.y, a0.z, a0.w, a1.x, a1.y, a1.z, a1.w};
            float br[8] = {b0.x, b0.y, b0.z, b0.w, b1v.x, b1v.y, b1v.z, b1v.w};
#pragma unroll
            for (int i = 0; i < 8; i++)
#pragma unroll
                for (int j = 0; j < 8; j++) c[i][j] += ar[i] * br[j];
        }
        __syncthreads();
    }

    const float* b2e = b2 + e * D_MODEL;
#pragma unroll
    for (int i = 0; i < 8; i++) {
        int m = ty * 8 + i;
        if (m < nr) {
            int token = g_rowToken[rs + m];
            float wgt = g_tokw[token];
            float* orow = out + (size_t)token * D_MODEL;
#pragma unroll
            for (int j = 0; j < 8; j++) {
                int n = n0 + tx * 8 + j;
                atomicAdd(&orow[n], wgt * (c[i][j] + b2e[n]));
            }
        }
    }
}

extern "C" void kernel_launch(void* const* d_in, const int* in_sizes, int n_in,
                              void* d_out, int out_size) {
    const float* x      = (const float*)d_in[0];
    const float* gate_w = (const float*)d_in[1];
    const float* w1     = (const float*)d_in[2];
    const float* b1     = (const float*)d_in[3];
    const float* w2     = (const float*)d_in[4];
    const float* b2     = (const float*)d_in[5];
    float* out = (float*)d_out;

    // 1. zero output + counters (graph-replay safe)
    init_kernel<<<(N_TOK * D_MODEL / 4 + 255) / 256, 256>>>(out);
    // 2. gating
    gate_kernel<<<N_TOK, 256>>>(x, gate_w);
    // 3. offsets + tiles
    setup_kernel<<<1, 1>>>();
    // 4. scatter tokens to expert-sorted rows
    scatter_kernel<<<(N_TOK + 255) / 256, 256>>>();
    // 5. fc1 grouped GEMM + GELU
    {
        dim3 g(MAX_TILES, H_DIM / 128);
        fc1_kernel<<<g, 256>>>(x, w1, b1);
    }
    // 6. fc2 grouped GEMM + weighted scatter-add
    {
        dim3 g(MAX_TILES, D_MODEL / 128);
        fc2_kernel<<<g, 256>>>(w2, b2, out);
    }
}

// round 5
// speedup vs baseline: 2.3895x; 2.3895x over previous
#include <cuda_runtime.h>
#include <math.h>
#include <stdint.h>

#define N_TOK   8192
#define D_MODEL 1024
#define H_DIM   512
#define N_EXP   8
#define TOPK    2
#define N_ASSIGN (N_TOK * TOPK)
#define TILE_M  128
#define MAX_TILES (N_ASSIGN / TILE_M + N_EXP)   // 136

// ------------------- device scratch -------------------
__device__ float g_h[(size_t)N_ASSIGN * H_DIM];
__device__ int   g_counts[N_EXP];
__device__ int   g_offsets[N_EXP + 1];
__device__ int   g_cursors[N_EXP];
__device__ int   g_rowToken[N_ASSIGN];
__device__ float g_tokw[N_TOK];
__device__ int   g_tokExperts[N_TOK * TOPK];
__device__ int   g_tileExpert[MAX_TILES];
__device__ int   g_tileRowStart[MAX_TILES];
__device__ int   g_tileRows[MAX_TILES];
__device__ int   g_numTiles;

// ------------------- helpers -------------------
__device__ __forceinline__ uint32_t f2tf(float f) {
    uint32_t u;
    asm("cvt.rna.tf32.f32 %0, %1;" : "=r"(u) : "f"(f));
    return u;
}
__device__ __forceinline__ void mma_tf32(float& c0, float& c1, float& c2, float& c3,
                                         uint32_t a0, uint32_t a1, uint32_t a2, uint32_t a3,
                                         uint32_t b0, uint32_t b1) {
    asm volatile("mma.sync.aligned.m16n8k8.row.col.f32.tf32.tf32.f32 "
                 "{%0,%1,%2,%3}, {%4,%5,%6,%7}, {%8,%9}, {%0,%1,%2,%3};"
                 : "+f"(c0), "+f"(c1), "+f"(c2), "+f"(c3)
                 : "r"(a0), "r"(a1), "r"(a2), "r"(a3), "r"(b0), "r"(b1));
}
__device__ __forceinline__ float gelu_exact(float v) {
    return 0.5f * v * (1.0f + erff(v * 0.70710678118654752f));
}

// ------------------- init -------------------
__global__ void init_kernel(float* __restrict__ out) {
    int idx = blockIdx.x * blockDim.x + threadIdx.x;
    if (idx < (N_TOK * D_MODEL) / 4)
        ((float4*)out)[idx] = make_float4(0.f, 0.f, 0.f, 0.f);
    if (idx < N_EXP) g_counts[idx] = 0;
}

// ------------------- gating -------------------
__global__ void gate_kernel(const float* __restrict__ x, const float* __restrict__ gw) {
    int n = blockIdx.x;
    int tid = threadIdx.x;
    const float* xr = x + (size_t)n * D_MODEL;
    float acc[N_EXP];
#pragma unroll
    for (int e = 0; e < N_EXP; e++) acc[e] = 0.f;
    for (int d = tid; d < D_MODEL; d += 256) {
        float xv = xr[d];
        const float* g = gw + d * N_EXP;
#pragma unroll
        for (int e = 0; e < N_EXP; e++) acc[e] += xv * g[e];
    }
#pragma unroll
    for (int off = 16; off > 0; off >>= 1)
#pragma unroll
        for (int e = 0; e < N_EXP; e++)
            acc[e] += __shfl_down_sync(0xffffffffu, acc[e], off);
    __shared__ float s[8][N_EXP];
    int w = tid >> 5, l = tid & 31;
    if (l == 0)
#pragma unroll
        for (int e = 0; e < N_EXP; e++) s[w][e] = acc[e];
    __syncthreads();
    if (tid == 0) {
        float p[N_EXP];
#pragma unroll
        for (int e = 0; e < N_EXP; e++) {
            float v = 0.f;
#pragma unroll
            for (int ww = 0; ww < 8; ww++) v += s[ww][e];
            p[e] = v;
        }
        float mx = p[0];
#pragma unroll
        for (int e = 1; e < N_EXP; e++) mx = fmaxf(mx, p[e]);
        float sum = 0.f;
#pragma unroll
        for (int e = 0; e < N_EXP; e++) { p[e] = expf(p[e] - mx); sum += p[e]; }
        float inv = 1.f / sum;
#pragma unroll
        for (int e = 0; e < N_EXP; e++) p[e] *= inv;
        int i1 = 0;
#pragma unroll
        for (int e = 1; e < N_EXP; e++) if (p[e] > p[i1]) i1 = e;
        int i2 = (i1 == 0) ? 1 : 0;
#pragma unroll
        for (int e = 0; e < N_EXP; e++) if (e != i1 && p[e] > p[i2]) i2 = e;
        g_tokw[n] = p[i1] + p[i2];
        g_tokExperts[2 * n + 0] = i1;
        g_tokExperts[2 * n + 1] = i2;
        atomicAdd(&g_counts[i1], 1);
        atomicAdd(&g_counts[i2], 1);
    }
}

// ------------------- setup + scatter -------------------
__global__ void setup_kernel() {
    int off = 0;
    for (int e = 0; e < N_EXP; e++) { g_offsets[e] = off; g_cursors[e] = off; off += g_counts[e]; }
    g_offsets[N_EXP] = off;
    int t = 0;
    for (int e = 0; e < N_EXP; e++) {
        int c = g_counts[e];
        for (int r = 0; r < c; r += TILE_M) {
            g_tileExpert[t] = e; g_tileRowStart[t] = g_offsets[e] + r;
            g_tileRows[t] = min(TILE_M, c - r); t++;
        }
    }
    g_numTiles = t;
}
__global__ void scatter_kernel() {
    int n = blockIdx.x * blockDim.x + threadIdx.x;
    if (n >= N_TOK) return;
#pragma unroll
    for (int k = 0; k < TOPK; k++) {
        int e = g_tokExperts[2 * n + k];
        int pos = atomicAdd(&g_cursors[e], 1);
        g_rowToken[pos] = n;
    }
}

// ------------------- tf32 mma.sync grouped GEMM -------------------
// Tile 128(M) x 128(N), BK=16. 8 warps: warp_m = wid&1 (x64), warp_n = wid>>1 (x32).
// Warp tile 64x32 -> 4x4 grid of m16n8k8.
// SMEM: As[2][128][20] (bank=4m+k, conflict-free), Bs[2][16][136] (bank=8k+n, conflict-free).
#define BK 16
#define ASTR 20
#define BSTR 136

struct Frag { float c[4][4][4]; };  // [mi][ni][reg]

template <int KDIM, bool FC1>
__device__ __forceinline__ void gemm_core(
    const float* __restrict__ aBase,   // FC1: x (gathered); FC2: g_h
    const float* __restrict__ bBase,   // weight [KDIM][N_total] row-major for this expert
    int nTotal, int n0, int rs, int nr, Frag& F)
{
    __shared__ uint32_t As[2][128][ASTR];
    __shared__ uint32_t Bs[2][BK][BSTR];

    int tid = threadIdx.x;
    int lane = tid & 31, wid = tid >> 5;
    int quad = lane >> 2, t4 = lane & 3;
    int wm = (wid & 1) * 64, wn = (wid >> 1) * 32;

    // A gather setup: 2 threads per row, 8 floats (2 float4) each
    int arow = tid >> 1;
    int acol0 = (tid & 1) * 8;
    const float* aptr;
    bool avalid;
    if (FC1) {
        avalid = arow < nr;
        aptr = avalid ? (aBase + (size_t)g_rowToken[rs + arow] * KDIM) : aBase;
    } else {
        avalid = true;
        int ar = rs + arow; if (ar >= N_ASSIGN) ar = N_ASSIGN - 1;
        aptr = aBase + (size_t)ar * KDIM;
    }
    // B: 16 threads/row group: row = tid>>4 (0..15), 2 float4 at cols (tid&15)*8
    int brow = tid >> 4;
    int bcol0 = (tid & 15) * 8;
    const float* bptr = bBase + (size_t)brow * nTotal + n0 + bcol0;

#pragma unroll
    for (int mi = 0; mi < 4; mi++)
#pragma unroll
        for (int ni = 0; ni < 4; ni++)
#pragma unroll
            for (int rr = 0; rr < 4; rr++) F.c[mi][ni][rr] = 0.f;

    // ---- prologue: load tile 0 ----
    {
#pragma unroll
        for (int j = 0; j < 2; j++) {
            float4 v = avalid ? *(const float4*)(aptr + acol0 + j * 4)
                              : make_float4(0.f, 0.f, 0.f, 0.f);
            uint32_t* d = &As[0][arow][acol0 + j * 4];
            d[0] = f2tf(v.x); d[1] = f2tf(v.y); d[2] = f2tf(v.z); d[3] = f2tf(v.w);
        }
#pragma unroll
        for (int j = 0; j < 2; j++) {
            float4 v = *(const float4*)(bptr + j * 4);
            uint32_t* d = &Bs[0][brow][bcol0 + j * 4];
            d[0] = f2tf(v.x); d[1] = f2tf(v.y); d[2] = f2tf(v.z); d[3] = f2tf(v.w);
        }
    }
    __syncthreads();

    const int NT = KDIM / BK;
    for (int t = 0; t < NT; t++) {
        int s = t & 1;
        float4 na[2], nb[2];
        bool more = (t + 1) < NT;
        if (more) {
            int k0 = (t + 1) * BK;
#pragma unroll
            for (int j = 0; j < 2; j++)
                na[j] = avalid ? *(const float4*)(aptr + k0 + acol0 + j * 4)
                               : make_float4(0.f, 0.f, 0.f, 0.f);
#pragma unroll
            for (int j = 0; j < 2; j++)
                nb[j] = *(const float4*)(bptr + (size_t)k0 * nTotal + j * 4);
        }
        // ---- compute on stage s ----
#pragma unroll
        for (int kk = 0; kk < BK / 8; kk++) {
            uint32_t a[4][4], b[4][2];
#pragma unroll
            for (int mi = 0; mi < 4; mi++) {
                int r0 = wm + mi * 16 + quad;
                a[mi][0] = As[s][r0][kk * 8 + t4];
                a[mi][1] = As[s][r0 + 8][kk * 8 + t4];
                a[mi][2] = As[s][r0][kk * 8 + t4 + 4];
                a[mi][3] = As[s][r0 + 8][kk * 8 + t4 + 4];
            }
#pragma unroll
            for (int ni = 0; ni < 4; ni++) {
                int cc = wn + ni * 8 + quad;
                b[ni][0] = Bs[s][kk * 8 + t4][cc];
                b[ni][1] = Bs[s][kk * 8 + t4 + 4][cc];
            }
#pragma unroll
            for (int mi = 0; mi < 4; mi++)
#pragma unroll
                for (int ni = 0; ni < 4; ni++)
                    mma_tf32(F.c[mi][ni][0], F.c[mi][ni][1], F.c[mi][ni][2], F.c[mi][ni][3],
                             a[mi][0], a[mi][1], a[mi][2], a[mi][3],
                             b[ni][0], b[ni][1]);
        }
        // ---- store next stage ----
        if (more) {
            int s1 = s ^ 1;
#pragma unroll
            for (int j = 0; j < 2; j++) {
                uint32_t* d = &As[s1][arow][acol0 + j * 4];
                d[0] = f2tf(na[j].x); d[1] = f2tf(na[j].y); d[2] = f2tf(na[j].z); d[3] = f2tf(na[j].w);
            }
#pragma unroll
            for (int j = 0; j < 2; j++) {
                uint32_t* d = &Bs[s1][brow][bcol0 + j * 4];
                d[0] = f2tf(nb[j].x); d[1] = f2tf(nb[j].y); d[2] = f2tf(nb[j].z); d[3] = f2tf(nb[j].w);
            }
        }
        __syncthreads();
    }
}

// fc1: h = gelu(x_gathered @ w1[e] + b1[e]); grid (MAX_TILES, H_DIM/128)
__global__ void __launch_bounds__(256, 2)
fc1_mma(const float* __restrict__ x, const float* __restrict__ w1,
        const float* __restrict__ b1) {
    int tile = blockIdx.x;
    if (tile >= g_numTiles) return;
    int e = g_tileExpert[tile], rs = g_tileRowStart[tile], nr = g_tileRows[tile];
    int n0 = blockIdx.y * 128;

    Frag F;
    gemm_core<D_MODEL, true>(x, w1 + (size_t)e * D_MODEL * H_DIM, H_DIM, n0, rs, nr, F);

    int tid = threadIdx.x, lane = tid & 31, wid = tid >> 5;
    int quad = lane >> 2, t4 = lane & 3;
    int wm = (wid & 1) * 64, wn = (wid >> 1) * 32;
    const float* b1e = b1 + e * H_DIM + n0;
#pragma unroll
    for (int mi = 0; mi < 4; mi++) {
#pragma unroll
        for (int half = 0; half < 2; half++) {
            int m = wm + mi * 16 + quad + half * 8;
            if (m < nr) {
                float* hrow = g_h + (size_t)(rs + m) * H_DIM + n0;
#pragma unroll
                for (int ni = 0; ni < 4; ni++) {
                    int cc = wn + ni * 8 + 2 * t4;
                    float v0 = F.c[mi][ni][half * 2 + 0] + b1e[cc];
                    float v1 = F.c[mi][ni][half * 2 + 1] + b1e[cc + 1];
                    float2 o = make_float2(gelu_exact(v0), gelu_exact(v1));
                    *(float2*)(hrow + cc) = o;
                }
            }
        }
    }
}

// fc2: out[token] += tokw * (h @ w2[e] + b2[e]); grid (MAX_TILES, D_MODEL/128)
__global__ void __launch_bounds__(256, 2)
fc2_mma(const float* __restrict__ w2, const float* __restrict__ b2,
        float* __restrict__ out) {
    int tile = blockIdx.x;
    if (tile >= g_numTiles) return;
    int e = g_tileExpert[tile], rs = g_tileRowStart[tile], nr = g_tileRows[tile];
    int n0 = blockIdx.y * 128;

    Frag F;
    gemm_core<H_DIM, false>(g_h, w2 + (size_t)e * H_DIM * D_MODEL, D_MODEL, n0, rs, nr, F);

    int tid = threadIdx.x, lane = tid & 31, wid = tid >> 5;
    int quad = lane >> 2, t4 = lane & 3;
    int wm = (wid & 1) * 64, wn = (wid >> 1) * 32;
    const float* b2e = b2 + e * D_MODEL + n0;
#pragma unroll
    for (int mi = 0; mi < 4; mi++) {
#pragma unroll
        for (int half = 0; half < 2; half++) {
            int m = wm + mi * 16 + quad + half * 8;
            if (m < nr) {
                int token = g_rowToken[rs + m];
                float wgt = g_tokw[token];
                float* orow = out + (size_t)token * D_MODEL + n0;
#pragma unroll
                for (int ni = 0; ni < 4; ni++) {
                    int cc = wn + ni * 8 + 2 * t4;
                    float v0 = F.c[mi][ni][half * 2 + 0] + b2e[cc];
                    float v1 = F.c[mi][ni][half * 2 + 1] + b2e[cc + 1];
                    atomicAdd(&orow[cc], wgt * v0);
                    atomicAdd(&orow[cc + 1], wgt * v1);
                }
            }
        }
    }
}

// ------------------- launch -------------------
extern "C" void kernel_launch(void* const* d_in, const int* in_sizes, int n_in,
                              void* d_out, int out_size) {
    const float* x      = (const float*)d_in[0];
    const float* gate_w = (const float*)d_in[1];
    const float* w1     = (const float*)d_in[2];
    const float* b1     = (const float*)d_in[3];
    const float* w2     = (const float*)d_in[4];
    const float* b2     = (const float*)d_in[5];
    float* out = (float*)d_out;

    init_kernel<<<(N_TOK * D_MODEL / 4 + 255) / 256, 256>>>(out);
    gate_kernel<<<N_TOK, 256>>>(x, gate_w);
    setup_kernel<<<1, 1>>>();
    scatter_kernel<<<(N_TOK + 255) / 256, 256>>>();
    {
        dim3 g(MAX_TILES, H_DIM / 128);
        fc1_mma<<<g, 256>>>(x, w1, b1);
    }
    {
        dim3 g(MAX_TILES, D_MODEL / 128);
        fc2_mma<<<g, 256>>>(w2, b2, out);
    }
}